// round 15
// baseline (speedup 1.0000x reference)
#include <cuda_runtime.h>
#include <cuda_fp16.h>
#include <cstdint>

// B=16, C=512, T=1024, L=77, S=1101(pad->1152), HEADS=8, D=64, GROUPS=32, CROSS=768

__device__ __half g_xnT [16 * 1024 * 512];     // [b][t][512]
__device__ __half g_qkvT[16 * 1024 * 1536];    // [b][t][1536]
__device__ __half g_cT  [16 * 77 * 768];       // [b][l][768]
__device__ __half g_ckvT[16 * 77 * 1024];      // [b][l][1024]
__device__ __half g_vT  [128 * 1152 * 64];     // [bh][s][d]  (BSS zero => pad rows 0)
__device__ __half g_aT  [16 * 1024 * 512];     // [b][t][512]
__device__ __half g_wq[1536 * 512];
__device__ __half g_wc[1024 * 768];
__device__ __half g_wp[512 * 512];

#define DINL __device__ __forceinline__

DINL void mma_f16(float* c, const uint32_t* a, uint32_t b0, uint32_t b1) {
    asm volatile(
        "mma.sync.aligned.m16n8k16.row.col.f32.f16.f16.f32 "
        "{%0,%1,%2,%3},{%4,%5,%6,%7},{%8,%9},{%0,%1,%2,%3};"
        : "+f"(c[0]), "+f"(c[1]), "+f"(c[2]), "+f"(c[3])
        : "r"(a[0]), "r"(a[1]), "r"(a[2]), "r"(a[3]), "r"(b0), "r"(b1));
}
DINL void ldsm4(uint32_t* r, uint32_t addr) {
    asm volatile(
        "ldmatrix.sync.aligned.m8n8.x4.shared.b16 {%0,%1,%2,%3}, [%4];"
        : "=r"(r[0]), "=r"(r[1]), "=r"(r[2]), "=r"(r[3]) : "r"(addr));
}
DINL void ldsm4t(uint32_t* r, uint32_t addr) {
    asm volatile(
        "ldmatrix.sync.aligned.m8n8.x4.trans.shared.b16 {%0,%1,%2,%3}, [%4];"
        : "=r"(r[0]), "=r"(r[1]), "=r"(r[2]), "=r"(r[3]) : "r"(addr));
}
DINL uint32_t pack_h2(float a, float b) {
    __half2 h = __floats2half2_rn(a, b);
    return *(uint32_t*)&h;
}
DINL uint32_t ex2_h2(float a, float b) {
    uint32_t in = pack_h2(a, b), out;
    asm("ex2.approx.f16x2 %0, %1;" : "=r"(out) : "r"(in));
    return out;
}
DINL uint32_t sa32(const void* p) {
    uint32_t a;
    asm("{\n\t.reg .u64 t;\n\tcvta.to.shared.u64 t, %1;\n\tcvt.u32.u64 %0, t;\n\t}"
        : "=r"(a) : "l"(p));
    return a;
}
DINL void cpa16(uint32_t dst, const void* src) {
    asm volatile("cp.async.cg.shared.global [%0], [%1], 16;" :: "r"(dst), "l"(src));
}
DINL void cpa16z(uint32_t dst, const void* src, int sz) {
    asm volatile("cp.async.cg.shared.global [%0], [%1], 16, %2;"
                 :: "r"(dst), "l"(src), "r"(sz));
}
DINL void cpa_commit() { asm volatile("cp.async.commit_group;" ::: "memory"); }
DINL void cpa_wait0()  { asm volatile("cp.async.wait_group 0;" ::: "memory"); }
DINL void cpa_wait1()  { asm volatile("cp.async.wait_group 1;" ::: "memory"); }

// ---------------------------------------------------------------------------
// GroupNorm(32), one global read; normalize + transpose + fp16 from smem.
// ---------------------------------------------------------------------------
__global__ __launch_bounds__(256)
void groupnorm_kernel(const float* __restrict__ x,
                      const float* __restrict__ gamma,
                      const float* __restrict__ beta,
                      __half* __restrict__ xnT)
{
    extern __shared__ float xs[];   // [16][1024]
    int b = blockIdx.x >> 5;
    int g = blockIdx.x & 31;
    const float* xp = x + ((size_t)b * 512 + (size_t)g * 16) * 1024;

    float s = 0.f, s2 = 0.f;
    for (int i = threadIdx.x; i < 16384; i += 256) {
        float v = xp[i];
        xs[i] = v;
        s += v; s2 += v * v;
    }
#pragma unroll
    for (int o = 16; o > 0; o >>= 1) {
        s  += __shfl_xor_sync(0xffffffffu, s, o);
        s2 += __shfl_xor_sync(0xffffffffu, s2, o);
    }
    __shared__ float ss[8], ss2[8];
    __shared__ float smean, sinv;
    int w = threadIdx.x >> 5;
    if ((threadIdx.x & 31) == 0) { ss[w] = s; ss2[w] = s2; }
    __syncthreads();
    if (threadIdx.x == 0) {
        float S = 0.f, S2 = 0.f;
#pragma unroll
        for (int i = 0; i < 8; i++) { S += ss[i]; S2 += ss2[i]; }
        float mean = S * (1.f / 16384.f);
        float var  = S2 * (1.f / 16384.f) - mean * mean;
        smean = mean;
        sinv  = rsqrtf(var + 1e-5f);
    }
    __syncthreads();
    float mean = smean, inv = sinv;

    float gm[16], bt[16];
#pragma unroll
    for (int ch = 0; ch < 16; ch++) {
        gm[ch] = gamma[g * 16 + ch] * inv;
        bt[ch] = beta[g * 16 + ch] - mean * gm[ch];
    }
#pragma unroll
    for (int seg = 0; seg < 4; seg++) {
        int t = seg * 256 + threadIdx.x;
        uint32_t wv[8];
#pragma unroll
        for (int c = 0; c < 8; c++) {
            float v0 = xs[(2 * c)     * 1024 + t] * gm[2 * c]     + bt[2 * c];
            float v1 = xs[(2 * c + 1) * 1024 + t] * gm[2 * c + 1] + bt[2 * c + 1];
            wv[c] = pack_h2(v0, v1);
        }
        __half* dst = xnT + ((size_t)b * 1024 + t) * 512 + g * 16;
        *(uint4*)dst = *(uint4*)&wv[0];
        *(uint4*)(dst + 8) = *(uint4*)&wv[4];
    }
}

// ---------------------------------------------------------------------------
__global__ __launch_bounds__(256)
void convW_all(const float* __restrict__ w0, __half* __restrict__ h0, int n0,
               const float* __restrict__ w1, __half* __restrict__ h1, int n1,
               const float* __restrict__ w2, __half* __restrict__ h2, int n2)
{
    int i = blockIdx.x * 256 + threadIdx.x;
    if (i < n0) { h0[i] = __float2half_rn(w0[i]); return; }
    i -= n0;
    if (i < n1) { h1[i] = __float2half_rn(w1[i]); return; }
    i -= n1;
    if (i < n2) { h2[i] = __float2half_rn(w2[i]); }
}

// c [b][768][77] fp32 -> cT [b][77][768] fp16
__global__ __launch_bounds__(256)
void prep_c_kernel(const float* __restrict__ c, __half* __restrict__ cT)
{
    __shared__ float tile[32][33];
    int t0 = blockIdx.x * 32, cb = blockIdx.y * 32, b = blockIdx.z;
    const float* ip = c + (size_t)b * 768 * 77;
    int tx = threadIdx.x & 31, ty = threadIdx.x >> 5;
#pragma unroll
    for (int i = 0; i < 4; i++) {
        int cr = ty + i * 8;
        tile[cr][tx] = (t0 + tx < 77) ? ip[(size_t)(cb + cr) * 77 + t0 + tx] : 0.f;
    }
    __syncthreads();
#pragma unroll
    for (int i = 0; i < 4; i++) {
        int tr = ty + i * 8;
        if (t0 + tr < 77)
            cT[(size_t)b * 77 * 768 + (size_t)(t0 + tr) * 768 + cb + tx] =
                __float2half_rn(tile[tx][tr]);
    }
}

// ---------------------------------------------------------------------------
// GEMM body: CTA tile 128m x 256n, BK=64, 8 warps (2m x 4n), warp tile 64x64.
// 3-stage cp.async ring; ldmatrix frags (1.0 wf/mma).
// Stage layout (words): A[128][36]=4608 | B[256][36]=9216 ; stride 13824.
// ---------------------------------------------------------------------------
DINL void gemm_at_body(const __half* __restrict__ A, const __half* __restrict__ W,
                       const float* __restrict__ bias, __half* __restrict__ oh,
                       __half* __restrict__ voutB,
                       int Mrows, int K, int ldo, int m0, int n0,
                       int vlo, int sOff, uint32_t sb, uint32_t* smp, int tid)
{
    int w = tid >> 5, lane = tid & 31;
    int g = lane >> 2, tg = lane & 3;
    int warp_m = w >> 2, warp_n = w & 3;
    int lr  = (lane & 7) + ((lane >> 3) & 1) * 8;
    int lk  = (lane >> 4) * 4;
    int bnt = lane >> 4;
    int bko = ((lane >> 3) & 1) * 4;
    int br  = lane & 7;

    float acc[4][8][4];
#pragma unroll
    for (int i = 0; i < 4; i++)
#pragma unroll
        for (int j = 0; j < 8; j++)
#pragma unroll
            for (int c = 0; c < 4; c++) acc[i][j][c] = 0.f;

    int nk = K >> 6;

    auto stage = [&](int c, int buf) {
        int OA = buf * 13824, OB = OA + 4608;
        int k0 = c * 64;
#pragma unroll
        for (int it = 0; it < 4; it++) {          // A: 128 rows
            int i = tid + it * 256;
            int row = i >> 3, seg = i & 7;
            int ar = (m0 + row < Mrows) ? (m0 + row) : 0;
            int sz = (m0 + row < Mrows) ? 16 : 0;
            cpa16z(sb + (OA + row * 36 + seg * 4) * 4,
                   A + (size_t)ar * K + k0 + seg * 8, sz);
        }
#pragma unroll
        for (int it = 0; it < 8; it++) {          // B: 256 rows
            int i = tid + it * 256;
            int row = i >> 3, seg = i & 7;
            cpa16(sb + (OB + row * 36 + seg * 4) * 4,
                  W + (size_t)(n0 + row) * K + k0 + seg * 8);
        }
    };

    stage(0, 0); cpa_commit();
    stage(1, 1); cpa_commit();

    for (int c = 0; c < nk; c++) {
        if (c < nk - 1) cpa_wait1(); else cpa_wait0();
        __syncthreads();
        if (c + 2 < nk) { stage(c + 2, (c + 2) % 3); cpa_commit(); }
        int OA = (c % 3) * 13824, OB = OA + 4608;
        uint32_t abase = sb + (OA + (warp_m * 64 + lr) * 36 + lk) * 4;
        uint32_t bbase = sb + (OB + (warp_n * 64 + bnt * 8 + br) * 36 + bko) * 4;
#pragma unroll
        for (int ks = 0; ks < 4; ks++) {
            int kb = ks * 8;
            uint32_t af[4][4];
#pragma unroll
            for (int mt = 0; mt < 4; mt++)
                ldsm4(af[mt], abase + (mt * 16 * 36 + kb) * 4);
            uint32_t bf[4][4];
#pragma unroll
            for (int p = 0; p < 4; p++)
                ldsm4(bf[p], bbase + (p * 16 * 36 + kb) * 4);
#pragma unroll
            for (int nt = 0; nt < 8; nt++) {
                uint32_t b0 = bf[nt >> 1][(nt & 1) * 2];
                uint32_t b1 = bf[nt >> 1][(nt & 1) * 2 + 1];
#pragma unroll
                for (int mt = 0; mt < 4; mt++)
                    mma_f16(acc[mt][nt], af[mt], b0, b1);
            }
        }
    }

#pragma unroll
    for (int mt = 0; mt < 4; mt++) {
#pragma unroll
        for (int rr = 0; rr < 2; rr++) {
            int m = m0 + warp_m * 64 + mt * 16 + rr * 8 + g;
            if (m < Mrows) {
#pragma unroll
                for (int nt = 0; nt < 8; nt++) {
                    int n = n0 + warp_n * 64 + nt * 8 + 2 * tg;
                    float v0 = acc[mt][nt][rr * 2]     + bias[n];
                    float v1 = acc[mt][nt][rr * 2 + 1] + bias[n + 1];
                    __half2 hh = __floats2half2_rn(v0, v1);
                    *(uint32_t*)(oh + (size_t)m * ldo + n) = *(uint32_t*)&hh;
                    int d0 = n - vlo;
                    if (d0 >= 0) {
                        size_t o = ((size_t)(d0 >> 6) * 1152 + sOff + m) * 64 + (d0 & 63);
                        *(uint32_t*)(voutB + o) = *(uint32_t*)&hh;
                    }
                }
            }
        }
    }
}

__global__ __launch_bounds__(256)
void gemm_qkv_ckv(const __half* __restrict__ xnT, const __half* __restrict__ wq,
                  const float* __restrict__ b_qkv,
                  const __half* __restrict__ cT, const __half* __restrict__ wc,
                  const float* __restrict__ b_c,
                  __half* __restrict__ qkvT, __half* __restrict__ ckvT,
                  __half* __restrict__ vT)
{
    extern __shared__ uint32_t sm[];
    int b = blockIdx.z;
    uint32_t sb = sa32(sm);
    int tid = threadIdx.x;
    __half* voutB = vT + (size_t)b * 8 * 1152 * 64;

    if (blockIdx.y < 8) {
        gemm_at_body(xnT + (size_t)b * 1024 * 512, wq, b_qkv,
                     qkvT + (size_t)b * 1024 * 1536, voutB,
                     1024, 512, 1536, blockIdx.y * 128, blockIdx.x * 256,
                     1024, 0, sb, sm, tid);
    } else {
        if (blockIdx.x >= 4) return;
        gemm_at_body(cT + (size_t)b * 77 * 768, wc, b_c,
                     ckvT + (size_t)b * 77 * 1024, voutB,
                     77, 768, 1024, 0, blockIdx.x * 256,
                     512, 1024, sb, sm, tid);
    }
}

// ---------------------------------------------------------------------------
// Flash attention (unchanged from R14): 256 thr, 128q, 64-key tiles,
// warp = 16q x 64k, P in regs, ex2.f16x2, ones-column row sums,
// ldmatrix (+trans for V), 3-stage cp.async K/V ring, 2 CTAs/SM.
// ---------------------------------------------------------------------------
__global__ __launch_bounds__(256, 2)
void attn_kernel(const __half* __restrict__ qkvT, const __half* __restrict__ ckvT,
                 const __half* __restrict__ vT, __half* __restrict__ aT)
{
    extern __shared__ uint32_t smw[];
    const int OQ = 0;
    const float L2E = 1.4426950408889634f;
    const uint32_t ONES2 = 0x3C003C00u;

    int t0 = blockIdx.x * 128;
    int h  = blockIdx.y;
    int b  = blockIdx.z;
    int bh = b * 8 + h;
    int tid = threadIdx.x;
    int w = tid >> 5, lane = tid & 31;
    int g = lane >> 2, tg = lane & 3;
    uint32_t sb = sa32(smw);
    int lr  = (lane & 7) + ((lane >> 3) & 1) * 8;
    int lk  = (lane >> 4) * 4;
    int bnt = lane >> 4;
    int bko = ((lane >> 3) & 1) * 4;
    int br  = lane & 7;
    int vr  = lane & 15;
    int vkw = (lane >> 4) * 4;

    auto stage_kv = [&](int kt, int buf) {
        int OKb = 4608 + buf * 4608;
        int OVb = OKb + 2304;
        if (kt < 16) {
            const __half* kp = qkvT + ((size_t)b * 1024 + kt * 64) * 1536 + 512 + h * 64;
#pragma unroll
            for (int it = 0; it < 2; it++) {
                int i = tid + it * 256, s = i >> 3, seg = i & 7;
                cpa16(sb + (OKb + s * 36 + seg * 4) * 4, kp + (size_t)s * 1536 + seg * 8);
            }
        } else {
            const __half* kp = ckvT + (size_t)b * 77 * 1024 + h * 64;
            int base = (kt - 16) * 64;
#pragma unroll
            for (int it = 0; it < 2; it++) {
                int i = tid + it * 256, s = i >> 3, seg = i & 7;
                int sl = base + s;
                int sr = (sl < 77) ? sl : 0;
                int sz = (sl < 77) ? 16 : 0;
                cpa16z(sb + (OKb + s * 36 + seg * 4) * 4,
                       kp + (size_t)sr * 1024 + seg * 8, sz);
            }
        }
        const __half* vp = vT + ((size_t)bh * 1152 + kt * 64) * 64;
#pragma unroll
        for (int it = 0; it < 2; it++) {
            int i = tid + it * 256, s = i >> 3, seg = i & 7;
            cpa16(sb + (OVb + s * 36 + seg * 4) * 4, vp + (size_t)s * 64 + seg * 8);
        }
    };

    {
        const __half* qp = qkvT + ((size_t)b * 1024 + t0) * 1536 + h * 64;
#pragma unroll
        for (int it = 0; it < 4; it++) {
            int i = tid + it * 256, row = i >> 3, seg = i & 7;
            cpa16(sb + (OQ + row * 36 + seg * 4) * 4, qp + (size_t)row * 1536 + seg * 8);
        }
    }
    stage_kv(0, 0); cpa_commit();
    stage_kv(1, 1); cpa_commit();

    float oacc[8][4];
#pragma unroll
    for (int nt = 0; nt < 8; nt++)
#pragma unroll
        for (int c = 0; c < 4; c++) oacc[nt][c] = 0.f;
    float lacc[4] = {0.f, 0.f, 0.f, 0.f};
    float m_run[2] = {-1e30f, -1e30f};
    int rb = w * 16;
    uint32_t qbase = sb + (OQ + (rb + lr) * 36 + lk) * 4;

    for (int kt = 0; kt < 18; kt++) {
        if (kt < 17) cpa_wait1(); else cpa_wait0();
        __syncthreads();
        if (kt + 2 < 18) { stage_kv(kt + 2, (kt + 2) % 3); cpa_commit(); }
        int OKb = 4608 + (kt % 3) * 4608;
        int OVb = OKb + 2304;
        uint32_t kbase = sb + (OKb + (bnt * 8 + br) * 36 + bko) * 4;
        uint32_t vbase = sb + (OVb + vr * 36 + vkw) * 4;

        float sacc[8][4];
#pragma unroll
        for (int nt = 0; nt < 8; nt++)
#pragma unroll
            for (int c = 0; c < 4; c++) sacc[nt][c] = 0.f;

#pragma unroll
        for (int ks = 0; ks < 4; ks++) {
            int kb = ks * 8;
            uint32_t af[4];
            ldsm4(af, qbase + kb * 4);
            uint32_t bf[4][4];
#pragma unroll
            for (int p = 0; p < 4; p++)
                ldsm4(bf[p], kbase + (p * 16 * 36 + kb) * 4);
#pragma unroll
            for (int nt = 0; nt < 8; nt++) {
                uint32_t b0 = bf[nt >> 1][(nt & 1) * 2];
                uint32_t b1 = bf[nt >> 1][(nt & 1) * 2 + 1];
                mma_f16(sacc[nt], af, b0, b1);
            }
        }

#pragma unroll
        for (int nt = 0; nt < 8; nt++)
#pragma unroll
            for (int c = 0; c < 4; c++) {
                float v = sacc[nt][c] * 0.125f;
                if (kt == 17 && (nt * 8 + 2 * tg + (c & 1)) >= 13) v = -1e30f;
                sacc[nt][c] = v;
            }

        float mx[2];
#pragma unroll
        for (int rr = 0; rr < 2; rr++) {
            float m = fmaxf(sacc[0][rr*2], sacc[0][rr*2+1]);
#pragma unroll
            for (int nt = 1; nt < 8; nt++) {
                m = fmaxf(m, sacc[nt][rr*2]);
                m = fmaxf(m, sacc[nt][rr*2+1]);
            }
            m = fmaxf(m, __shfl_xor_sync(0xffffffffu, m, 1));
            m = fmaxf(m, __shfl_xor_sync(0xffffffffu, m, 2));
            mx[rr] = m;
        }
        float nm[2], corr[2], nml[2];
#pragma unroll
        for (int rr = 0; rr < 2; rr++) {
            nm[rr] = fmaxf(m_run[rr], mx[rr]);
            corr[rr] = __expf(m_run[rr] - nm[rr]);
            m_run[rr] = nm[rr];
            nml[rr] = nm[rr] * L2E;
        }
#pragma unroll
        for (int nt = 0; nt < 8; nt++) {
            oacc[nt][0] *= corr[0];
            oacc[nt][1] *= corr[0];
            oacc[nt][2] *= corr[1];
            oacc[nt][3] *= corr[1];
        }
        lacc[0] *= corr[0]; lacc[1] *= corr[0];
        lacc[2] *= corr[1]; lacc[3] *= corr[1];

#pragma unroll
        for (int j = 0; j < 4; j++) {
            uint32_t pa[4];
            pa[0] = ex2_h2(fmaf(sacc[2*j  ][0], L2E, -nml[0]),
                           fmaf(sacc[2*j  ][1], L2E, -nml[0]));
            pa[1] = ex2_h2(fmaf(sacc[2*j  ][2], L2E, -nml[1]),
                           fmaf(sacc[2*j  ][3], L2E, -nml[1]));
            pa[2] = ex2_h2(fmaf(sacc[2*j+1][0], L2E, -nml[0]),
                           fmaf(sacc[2*j+1][1], L2E, -nml[0]));
            pa[3] = ex2_h2(fmaf(sacc[2*j+1][2], L2E, -nml[1]),
                           fmaf(sacc[2*j+1][3], L2E, -nml[1]));
            uint32_t vf[4][4];
#pragma unroll
            for (int p = 0; p < 4; p++)
                ldsm4t(vf[p], vbase + (j * 16 * 36 + p * 8) * 4);
#pragma unroll
            for (int nt = 0; nt < 8; nt++) {
                uint32_t b0 = vf[nt >> 1][(nt & 1) * 2];
                uint32_t b1 = vf[nt >> 1][(nt & 1) * 2 + 1];
                mma_f16(oacc[nt], pa, b0, b1);
            }
            mma_f16(lacc, pa, ONES2, ONES2);
        }
    }

    float inv[2] = {1.f / lacc[0], 1.f / lacc[2]};
#pragma unroll
    for (int nt = 0; nt < 8; nt++)
#pragma unroll
        for (int rr = 0; rr < 2; rr++) {
            int t = t0 + rb + rr * 8 + g;
            int d = nt * 8 + 2 * tg;
            float v0 = oacc[nt][rr*2]     * inv[rr];
            float v1 = oacc[nt][rr*2 + 1] * inv[rr];
            *(uint32_t*)(aT + ((size_t)b * 1024 + t) * 512 + h * 64 + d) = pack_h2(v0, v1);
        }
}

// ---------------------------------------------------------------------------
// proj: 128m(ch) x 256n(t) tiles, warp 64x64, 3-stage ring, ldmatrix.
// out[b][m][n] = sum_k W[m][k]*aT[b][n][k] + bias + x
// ---------------------------------------------------------------------------
__global__ __launch_bounds__(256)
void gemm_WA(const __half* __restrict__ W, const __half* __restrict__ Bm,
             const float* __restrict__ bias, const float* __restrict__ res,
             float* __restrict__ out)
{
    extern __shared__ uint32_t sm[];
    const int K = 512, N = 1024;

    int b = blockIdx.z;
    const __half* Bp = Bm + (size_t)b * 1024 * 512;
    float* op = out + (size_t)b * 512 * 1024;
    const float* rp = res + (size_t)b * 512 * 1024;

    int tid = threadIdx.x, w = tid >> 5, lane = tid & 31;
    int g = lane >> 2, tg = lane & 3;
    int warp_m = w >> 2, warp_n = w & 3;
    int m0 = blockIdx.y * 128, n0 = blockIdx.x * 256;
    uint32_t sb = sa32(sm);
    int lr  = (lane & 7) + ((lane >> 3) & 1) * 8;
    int lk  = (lane >> 4) * 4;
    int bnt = lane >> 4;
    int bko = ((lane >> 3) & 1) * 4;
    int br  = lane & 7;

    float acc[4][8][4];
#pragma unroll
    for (int i = 0; i < 4; i++)
#pragma unroll
        for (int j = 0; j < 8; j++)
#pragma unroll
            for (int c = 0; c < 4; c++) acc[i][j][c] = 0.f;

    auto stage = [&](int c, int buf) {
        int OA = buf * 13824, OB = OA + 4608;
        int k0 = c * 64;
#pragma unroll
        for (int it = 0; it < 4; it++) {
            int i = tid + it * 256;
            int row = i >> 3, seg = i & 7;
            cpa16(sb + (OA + row * 36 + seg * 4) * 4,
                  W + (size_t)(m0 + row) * K + k0 + seg * 8);
        }
#pragma unroll
        for (int it = 0; it < 8; it++) {
            int i = tid + it * 256;
            int row = i >> 3, seg = i & 7;
            cpa16(sb + (OB + row * 36 + seg * 4) * 4,
                  Bp + (size_t)(n0 + row) * K + k0 + seg * 8);
        }
    };

    stage(0, 0); cpa_commit();
    stage(1, 1); cpa_commit();

    for (int c = 0; c < 8; c++) {
        if (c < 7) cpa_wait1(); else cpa_wait0();
        __syncthreads();
        if (c + 2 < 8) { stage(c + 2, (c + 2) % 3); cpa_commit(); }
        int OA = (c % 3) * 13824, OB = OA + 4608;
        uint32_t abase = sb + (OA + (warp_m * 64 + lr) * 36 + lk) * 4;
        uint32_t bbase = sb + (OB + (warp_n * 64 + bnt * 8 + br) * 36 + bko) * 4;
#pragma unroll
        for (int ks = 0; ks < 4; ks++) {
            int kb = ks * 8;
            uint32_t af[4][4];
#pragma unroll
            for (int mt = 0; mt < 4; mt++)
                ldsm4(af[mt], abase + (mt * 16 * 36 + kb) * 4);
            uint32_t bf[4][4];
#pragma unroll
            for (int p = 0; p < 4; p++)
                ldsm4(bf[p], bbase + (p * 16 * 36 + kb) * 4);
#pragma unroll
            for (int nt = 0; nt < 8; nt++) {
                uint32_t b0 = bf[nt >> 1][(nt & 1) * 2];
                uint32_t b1 = bf[nt >> 1][(nt & 1) * 2 + 1];
#pragma unroll
                for (int mt = 0; mt < 4; mt++)
                    mma_f16(acc[mt][nt], af[mt], b0, b1);
            }
        }
    }

#pragma unroll
    for (int mt = 0; mt < 4; mt++) {
#pragma unroll
        for (int rr = 0; rr < 2; rr++) {
            int m = m0 + warp_m * 64 + mt * 16 + rr * 8 + g;
            float bi = bias[m];
#pragma unroll
            for (int nt = 0; nt < 8; nt++) {
#pragma unroll
                for (int ci = 0; ci < 2; ci++) {
                    int n = n0 + warp_n * 64 + nt * 8 + 2 * tg + ci;
                    op[(size_t)m * N + n] = acc[mt][nt][rr * 2 + ci] + bi
                                          + rp[(size_t)m * N + n];
                }
            }
        }
    }
}

// ---------------------------------------------------------------------------
extern "C" void kernel_launch(void* const* d_in, const int* in_sizes, int n_in,
                              void* d_out, int out_size)
{
    const float* x     = (const float*)d_in[0];
    const float* c     = (const float*)d_in[1];
    const float* gamma = (const float*)d_in[2];
    const float* beta  = (const float*)d_in[3];
    const float* w_qkv = (const float*)d_in[4];
    const float* b_qkv = (const float*)d_in[5];
    const float* w_c   = (const float*)d_in[6];
    const float* b_c   = (const float*)d_in[7];
    const float* w_p   = (const float*)d_in[8];
    const float* b_p   = (const float*)d_in[9];
    float* out = (float*)d_out;

    __half *xnT, *qkvT, *cT, *ckvT, *vT, *aT, *wq, *wc, *wp;
    cudaGetSymbolAddress((void**)&xnT,  g_xnT);
    cudaGetSymbolAddress((void**)&qkvT, g_qkvT);
    cudaGetSymbolAddress((void**)&cT,   g_cT);
    cudaGetSymbolAddress((void**)&ckvT, g_ckvT);
    cudaGetSymbolAddress((void**)&vT,   g_vT);
    cudaGetSymbolAddress((void**)&aT,   g_aT);
    cudaGetSymbolAddress((void**)&wq,   g_wq);
    cudaGetSymbolAddress((void**)&wc,   g_wc);
    cudaGetSymbolAddress((void**)&wp,   g_wp);

    static bool attr_done = false;
    if (!attr_done) {
        cudaFuncSetAttribute(groupnorm_kernel, cudaFuncAttributeMaxDynamicSharedMemorySize, 65536);
        cudaFuncSetAttribute(gemm_qkv_ckv, cudaFuncAttributeMaxDynamicSharedMemorySize, 165888);
        cudaFuncSetAttribute(gemm_WA, cudaFuncAttributeMaxDynamicSharedMemorySize, 165888);
        cudaFuncSetAttribute(attn_kernel, cudaFuncAttributeMaxDynamicSharedMemorySize, 73728);
        attr_done = true;
    }

    groupnorm_kernel<<<512, 256, 65536>>>(x, gamma, beta, xnT);
    convW_all<<<7168, 256>>>(w_qkv, wq, 1536 * 512,
                             w_c, wc, 1024 * 768,
                             w_p, wp, 512 * 512);
    prep_c_kernel<<<dim3(3, 24, 16), 256>>>(c, cT);

    // qkv tiles: x<6 (n=256 each), y<8 (m=128); ckv: y==8, x<4
    gemm_qkv_ckv<<<dim3(6, 9, 16), 256, 165888>>>(xnT, wq, b_qkv, cT, wc, b_c,
                                                  qkvT, ckvT, vT);

    attn_kernel<<<dim3(8, 8, 16), 256, 73728>>>(qkvT, ckvT, vT, aT);

    gemm_WA<<<dim3(4, 4, 16), 256, 165888>>>(wp, aT, b_p, x, out);
}

// round 16
// speedup vs baseline: 1.0756x; 1.0756x over previous
#include <cuda_runtime.h>
#include <cuda_fp16.h>
#include <cstdint>

// B=16, C=512, T=1024, L=77, S=1101(pad->1152), HEADS=8, D=64, GROUPS=32, CROSS=768

__device__ __half g_xnT [16 * 1024 * 512];     // [b][t][512]
__device__ __half g_qkvT[16 * 1024 * 1536];    // [b][t][1536]
__device__ __half g_cT  [16 * 77 * 768];       // [b][l][768]
__device__ __half g_ckvT[16 * 77 * 1024];      // [b][l][1024]
__device__ __half g_vT  [128 * 1152 * 64];     // [bh][s][d]  (BSS zero => pad rows 0)
__device__ __half g_aT  [16 * 1024 * 512];     // [b][t][512]
__device__ __half g_wq[1536 * 512];
__device__ __half g_wc[1024 * 768];
__device__ __half g_wp[512 * 512];

#define DINL __device__ __forceinline__

DINL void mma_f16(float* c, const uint32_t* a, uint32_t b0, uint32_t b1) {
    asm volatile(
        "mma.sync.aligned.m16n8k16.row.col.f32.f16.f16.f32 "
        "{%0,%1,%2,%3},{%4,%5,%6,%7},{%8,%9},{%0,%1,%2,%3};"
        : "+f"(c[0]), "+f"(c[1]), "+f"(c[2]), "+f"(c[3])
        : "r"(a[0]), "r"(a[1]), "r"(a[2]), "r"(a[3]), "r"(b0), "r"(b1));
}
DINL void ldsm4(uint32_t* r, uint32_t addr) {
    asm volatile(
        "ldmatrix.sync.aligned.m8n8.x4.shared.b16 {%0,%1,%2,%3}, [%4];"
        : "=r"(r[0]), "=r"(r[1]), "=r"(r[2]), "=r"(r[3]) : "r"(addr));
}
DINL void ldsm4t(uint32_t* r, uint32_t addr) {
    asm volatile(
        "ldmatrix.sync.aligned.m8n8.x4.trans.shared.b16 {%0,%1,%2,%3}, [%4];"
        : "=r"(r[0]), "=r"(r[1]), "=r"(r[2]), "=r"(r[3]) : "r"(addr));
}
DINL uint32_t pack_h2(float a, float b) {
    __half2 h = __floats2half2_rn(a, b);
    return *(uint32_t*)&h;
}
DINL uint32_t ex2_h2(float a, float b) {
    uint32_t in = pack_h2(a, b), out;
    asm("ex2.approx.f16x2 %0, %1;" : "=r"(out) : "r"(in));
    return out;
}
DINL uint32_t sa32(const void* p) {
    uint32_t a;
    asm("{\n\t.reg .u64 t;\n\tcvta.to.shared.u64 t, %1;\n\tcvt.u32.u64 %0, t;\n\t}"
        : "=r"(a) : "l"(p));
    return a;
}
DINL void cpa16(uint32_t dst, const void* src) {
    asm volatile("cp.async.cg.shared.global [%0], [%1], 16;" :: "r"(dst), "l"(src));
}
DINL void cpa16z(uint32_t dst, const void* src, int sz) {
    asm volatile("cp.async.cg.shared.global [%0], [%1], 16, %2;"
                 :: "r"(dst), "l"(src), "r"(sz));
}
DINL void cpa_commit() { asm volatile("cp.async.commit_group;" ::: "memory"); }
DINL void cpa_wait0()  { asm volatile("cp.async.wait_group 0;" ::: "memory"); }
DINL void cpa_wait1()  { asm volatile("cp.async.wait_group 1;" ::: "memory"); }

// ---------------------------------------------------------------------------
// GroupNorm(32), one global read; normalize + transpose + fp16 from smem.
// ---------------------------------------------------------------------------
__global__ __launch_bounds__(256)
void groupnorm_kernel(const float* __restrict__ x,
                      const float* __restrict__ gamma,
                      const float* __restrict__ beta,
                      __half* __restrict__ xnT)
{
    extern __shared__ float xs[];   // [16][1024]
    int b = blockIdx.x >> 5;
    int g = blockIdx.x & 31;
    const float* xp = x + ((size_t)b * 512 + (size_t)g * 16) * 1024;

    float s = 0.f, s2 = 0.f;
    for (int i = threadIdx.x; i < 16384; i += 256) {
        float v = xp[i];
        xs[i] = v;
        s += v; s2 += v * v;
    }
#pragma unroll
    for (int o = 16; o > 0; o >>= 1) {
        s  += __shfl_xor_sync(0xffffffffu, s, o);
        s2 += __shfl_xor_sync(0xffffffffu, s2, o);
    }
    __shared__ float ss[8], ss2[8];
    __shared__ float smean, sinv;
    int w = threadIdx.x >> 5;
    if ((threadIdx.x & 31) == 0) { ss[w] = s; ss2[w] = s2; }
    __syncthreads();
    if (threadIdx.x == 0) {
        float S = 0.f, S2 = 0.f;
#pragma unroll
        for (int i = 0; i < 8; i++) { S += ss[i]; S2 += ss2[i]; }
        float mean = S * (1.f / 16384.f);
        float var  = S2 * (1.f / 16384.f) - mean * mean;
        smean = mean;
        sinv  = rsqrtf(var + 1e-5f);
    }
    __syncthreads();
    float mean = smean, inv = sinv;

    float gm[16], bt[16];
#pragma unroll
    for (int ch = 0; ch < 16; ch++) {
        gm[ch] = gamma[g * 16 + ch] * inv;
        bt[ch] = beta[g * 16 + ch] - mean * gm[ch];
    }
#pragma unroll
    for (int seg = 0; seg < 4; seg++) {
        int t = seg * 256 + threadIdx.x;
        uint32_t wv[8];
#pragma unroll
        for (int c = 0; c < 8; c++) {
            float v0 = xs[(2 * c)     * 1024 + t] * gm[2 * c]     + bt[2 * c];
            float v1 = xs[(2 * c + 1) * 1024 + t] * gm[2 * c + 1] + bt[2 * c + 1];
            wv[c] = pack_h2(v0, v1);
        }
        __half* dst = xnT + ((size_t)b * 1024 + t) * 512 + g * 16;
        *(uint4*)dst = *(uint4*)&wv[0];
        *(uint4*)(dst + 8) = *(uint4*)&wv[4];
    }
}

// ---------------------------------------------------------------------------
// fused prep: weight fp32->fp16 (blocks [0, 7168)) + c transpose (rest)
// ---------------------------------------------------------------------------
__global__ __launch_bounds__(256)
void prep_all(const float* __restrict__ w0, __half* __restrict__ h0, int n0,
              const float* __restrict__ w1, __half* __restrict__ h1, int n1,
              const float* __restrict__ w2, __half* __restrict__ h2, int n2,
              const float* __restrict__ c, __half* __restrict__ cT, int nconv)
{
    __shared__ float tile[32][33];
    if ((int)blockIdx.x < nconv) {
        int i = blockIdx.x * 256 + threadIdx.x;
        if (i < n0) { h0[i] = __float2half_rn(w0[i]); return; }
        i -= n0;
        if (i < n1) { h1[i] = __float2half_rn(w1[i]); return; }
        i -= n1;
        if (i < n2) { h2[i] = __float2half_rn(w2[i]); }
        return;
    }
    int idx = blockIdx.x - nconv;               // 0..1151
    int t0 = (idx % 3) * 32;
    int cb = ((idx / 3) % 24) * 32;
    int b  = idx / 72;
    const float* ip = c + (size_t)b * 768 * 77;
    int tx = threadIdx.x & 31, ty = threadIdx.x >> 5;
#pragma unroll
    for (int i = 0; i < 4; i++) {
        int cr = ty + i * 8;
        tile[cr][tx] = (t0 + tx < 77) ? ip[(size_t)(cb + cr) * 77 + t0 + tx] : 0.f;
    }
    __syncthreads();
#pragma unroll
    for (int i = 0; i < 4; i++) {
        int tr = ty + i * 8;
        if (t0 + tr < 77)
            cT[(size_t)b * 77 * 768 + (size_t)(t0 + tr) * 768 + cb + tx] =
                __float2half_rn(tile[tx][tr]);
    }
}

// ---------------------------------------------------------------------------
// fused qkv + ckv GEMM (R14): 128x128 tile, warp 64x32, 3-stage ring,
// ldmatrix frags; V epilogue writes s-major vT[bh][s][64] coalesced.
// ---------------------------------------------------------------------------
DINL void gemm_at_body(const __half* __restrict__ A, const __half* __restrict__ W,
                       const float* __restrict__ bias, __half* __restrict__ oh,
                       __half* __restrict__ voutB,
                       int Mrows, int K, int ldo, int m0, int n0,
                       int vlo, int sOff, uint32_t sb, uint32_t* sm, int tid)
{
    int w = tid >> 5, lane = tid & 31;
    int g = lane >> 2, tg = lane & 3;
    int warp_m = w >> 2, warp_n = w & 3;
    int lr  = (lane & 7) + ((lane >> 3) & 1) * 8;
    int lk  = (lane >> 4) * 4;
    int bnt = lane >> 4;
    int bko = ((lane >> 3) & 1) * 4;
    int br  = lane & 7;

    float acc[4][4][4];
#pragma unroll
    for (int i = 0; i < 4; i++)
#pragma unroll
        for (int j = 0; j < 4; j++)
#pragma unroll
            for (int c = 0; c < 4; c++) acc[i][j][c] = 0.f;

    int nk = K >> 6;

    auto stage = [&](int c, int buf) {
        int OA = buf * 9216, OB = OA + 4608;
        int k0 = c * 64;
#pragma unroll
        for (int it = 0; it < 4; it++) {
            int i = tid + it * 256;
            int row = i >> 3, seg = i & 7;
            int ar = (m0 + row < Mrows) ? (m0 + row) : 0;
            int sz = (m0 + row < Mrows) ? 16 : 0;
            cpa16z(sb + (OA + row * 36 + seg * 4) * 4,
                   A + (size_t)ar * K + k0 + seg * 8, sz);
            cpa16(sb + (OB + row * 36 + seg * 4) * 4,
                  W + (size_t)(n0 + row) * K + k0 + seg * 8);
        }
    };

    stage(0, 0); cpa_commit();
    stage(1, 1); cpa_commit();

    for (int c = 0; c < nk; c++) {
        if (c < nk - 1) cpa_wait1(); else cpa_wait0();
        __syncthreads();
        if (c + 2 < nk) { stage(c + 2, (c + 2) % 3); cpa_commit(); }
        int OA = (c % 3) * 9216, OB = OA + 4608;
        uint32_t abase = sb + (OA + (warp_m * 64 + lr) * 36 + lk) * 4;
        uint32_t bbase = sb + (OB + (warp_n * 32 + bnt * 8 + br) * 36 + bko) * 4;
#pragma unroll
        for (int ks = 0; ks < 4; ks++) {
            int kb = ks * 8;
            uint32_t af[4][4];
#pragma unroll
            for (int mt = 0; mt < 4; mt++)
                ldsm4(af[mt], abase + (mt * 16 * 36 + kb) * 4);
            uint32_t bf[2][4];
#pragma unroll
            for (int p = 0; p < 2; p++)
                ldsm4(bf[p], bbase + (p * 16 * 36 + kb) * 4);
#pragma unroll
            for (int nt = 0; nt < 4; nt++) {
                uint32_t b0 = bf[nt >> 1][(nt & 1) * 2];
                uint32_t b1 = bf[nt >> 1][(nt & 1) * 2 + 1];
#pragma unroll
                for (int mt = 0; mt < 4; mt++)
                    mma_f16(acc[mt][nt], af[mt], b0, b1);
            }
        }
    }

#pragma unroll
    for (int mt = 0; mt < 4; mt++) {
#pragma unroll
        for (int rr = 0; rr < 2; rr++) {
            int m = m0 + warp_m * 64 + mt * 16 + rr * 8 + g;
            if (m < Mrows) {
#pragma unroll
                for (int nt = 0; nt < 4; nt++) {
                    int n = n0 + warp_n * 32 + nt * 8 + 2 * tg;
                    float v0 = acc[mt][nt][rr * 2]     + bias[n];
                    float v1 = acc[mt][nt][rr * 2 + 1] + bias[n + 1];
                    __half2 hh = __floats2half2_rn(v0, v1);
                    *(uint32_t*)(oh + (size_t)m * ldo + n) = *(uint32_t*)&hh;
                    int d0 = n - vlo;
                    if (d0 >= 0) {
                        size_t o = ((size_t)(d0 >> 6) * 1152 + sOff + m) * 64 + (d0 & 63);
                        *(uint32_t*)(voutB + o) = *(uint32_t*)&hh;
                    }
                }
            }
        }
    }
}

__global__ __launch_bounds__(256, 2)
void gemm_qkv_ckv(const __half* __restrict__ xnT, const __half* __restrict__ wq,
                  const float* __restrict__ b_qkv,
                  const __half* __restrict__ cT, const __half* __restrict__ wc,
                  const float* __restrict__ b_c,
                  __half* __restrict__ qkvT, __half* __restrict__ ckvT,
                  __half* __restrict__ vT)
{
    extern __shared__ uint32_t sm[];
    int b = blockIdx.z;
    uint32_t sb = sa32(sm);
    int tid = threadIdx.x;
    __half* voutB = vT + (size_t)b * 8 * 1152 * 64;

    if (blockIdx.y < 8) {
        gemm_at_body(xnT + (size_t)b * 1024 * 512, wq, b_qkv,
                     qkvT + (size_t)b * 1024 * 1536, voutB,
                     1024, 512, 1536, blockIdx.y * 128, blockIdx.x * 128,
                     1024, 0, sb, sm, tid);
    } else {
        if (blockIdx.x >= 8) return;
        gemm_at_body(cT + (size_t)b * 77 * 768, wc, b_c,
                     ckvT + (size_t)b * 77 * 1024, voutB,
                     77, 768, 1024, 0, blockIdx.x * 128,
                     512, 1024, sb, sm, tid);
    }
}

// ---------------------------------------------------------------------------
// Flash attention (R14): 256 thr, 128q, 64-key tiles, warp = 16q x 64k,
// P in regs, ex2.f16x2, ones-column row sums, ldmatrix (+trans for V),
// 3-stage cp.async K/V ring, 2 CTAs/SM.
// smem words: Q[128][36]=4608 | stage x3 (K 2304 + V 2304) = 18432 (73728B)
// ---------------------------------------------------------------------------
__global__ __launch_bounds__(256, 2)
void attn_kernel(const __half* __restrict__ qkvT, const __half* __restrict__ ckvT,
                 const __half* __restrict__ vT, __half* __restrict__ aT)
{
    extern __shared__ uint32_t smw[];
    const int OQ = 0;
    const float L2E = 1.4426950408889634f;
    const uint32_t ONES2 = 0x3C003C00u;

    int t0 = blockIdx.x * 128;
    int h  = blockIdx.y;
    int b  = blockIdx.z;
    int bh = b * 8 + h;
    int tid = threadIdx.x;
    int w = tid >> 5, lane = tid & 31;
    int g = lane >> 2, tg = lane & 3;
    uint32_t sb = sa32(smw);
    int lr  = (lane & 7) + ((lane >> 3) & 1) * 8;
    int lk  = (lane >> 4) * 4;
    int bnt = lane >> 4;
    int bko = ((lane >> 3) & 1) * 4;
    int br  = lane & 7;
    int vr  = lane & 15;
    int vkw = (lane >> 4) * 4;

    auto stage_kv = [&](int kt, int buf) {
        int OKb = 4608 + buf * 4608;
        int OVb = OKb + 2304;
        if (kt < 16) {
            const __half* kp = qkvT + ((size_t)b * 1024 + kt * 64) * 1536 + 512 + h * 64;
#pragma unroll
            for (int it = 0; it < 2; it++) {
                int i = tid + it * 256, s = i >> 3, seg = i & 7;
                cpa16(sb + (OKb + s * 36 + seg * 4) * 4, kp + (size_t)s * 1536 + seg * 8);
            }
        } else {
            const __half* kp = ckvT + (size_t)b * 77 * 1024 + h * 64;
            int base = (kt - 16) * 64;
#pragma unroll
            for (int it = 0; it < 2; it++) {
                int i = tid + it * 256, s = i >> 3, seg = i & 7;
                int sl = base + s;
                int sr = (sl < 77) ? sl : 0;
                int sz = (sl < 77) ? 16 : 0;
                cpa16z(sb + (OKb + s * 36 + seg * 4) * 4,
                       kp + (size_t)sr * 1024 + seg * 8, sz);
            }
        }
        const __half* vp = vT + ((size_t)bh * 1152 + kt * 64) * 64;
#pragma unroll
        for (int it = 0; it < 2; it++) {
            int i = tid + it * 256, s = i >> 3, seg = i & 7;
            cpa16(sb + (OVb + s * 36 + seg * 4) * 4, vp + (size_t)s * 64 + seg * 8);
        }
    };

    {
        const __half* qp = qkvT + ((size_t)b * 1024 + t0) * 1536 + h * 64;
#pragma unroll
        for (int it = 0; it < 4; it++) {
            int i = tid + it * 256, row = i >> 3, seg = i & 7;
            cpa16(sb + (OQ + row * 36 + seg * 4) * 4, qp + (size_t)row * 1536 + seg * 8);
        }
    }
    stage_kv(0, 0); cpa_commit();
    stage_kv(1, 1); cpa_commit();

    float oacc[8][4];
#pragma unroll
    for (int nt = 0; nt < 8; nt++)
#pragma unroll
        for (int c = 0; c < 4; c++) oacc[nt][c] = 0.f;
    float lacc[4] = {0.f, 0.f, 0.f, 0.f};
    float m_run[2] = {-1e30f, -1e30f};
    int rb = w * 16;
    uint32_t qbase = sb + (OQ + (rb + lr) * 36 + lk) * 4;

    for (int kt = 0; kt < 18; kt++) {
        if (kt < 17) cpa_wait1(); else cpa_wait0();
        __syncthreads();
        if (kt + 2 < 18) { stage_kv(kt + 2, (kt + 2) % 3); cpa_commit(); }
        int OKb = 4608 + (kt % 3) * 4608;
        int OVb = OKb + 2304;
        uint32_t kbase = sb + (OKb + (bnt * 8 + br) * 36 + bko) * 4;
        uint32_t vbase = sb + (OVb + vr * 36 + vkw) * 4;

        float sacc[8][4];
#pragma unroll
        for (int nt = 0; nt < 8; nt++)
#pragma unroll
            for (int c = 0; c < 4; c++) sacc[nt][c] = 0.f;

#pragma unroll
        for (int ks = 0; ks < 4; ks++) {
            int kb = ks * 8;
            uint32_t af[4];
            ldsm4(af, qbase + kb * 4);
            uint32_t bf[4][4];
#pragma unroll
            for (int p = 0; p < 4; p++)
                ldsm4(bf[p], kbase + (p * 16 * 36 + kb) * 4);
#pragma unroll
            for (int nt = 0; nt < 8; nt++) {
                uint32_t b0 = bf[nt >> 1][(nt & 1) * 2];
                uint32_t b1 = bf[nt >> 1][(nt & 1) * 2 + 1];
                mma_f16(sacc[nt], af, b0, b1);
            }
        }

#pragma unroll
        for (int nt = 0; nt < 8; nt++)
#pragma unroll
            for (int c = 0; c < 4; c++) {
                float v = sacc[nt][c] * 0.125f;
                if (kt == 17 && (nt * 8 + 2 * tg + (c & 1)) >= 13) v = -1e30f;
                sacc[nt][c] = v;
            }

        float mx[2];
#pragma unroll
        for (int rr = 0; rr < 2; rr++) {
            float m = fmaxf(sacc[0][rr*2], sacc[0][rr*2+1]);
#pragma unroll
            for (int nt = 1; nt < 8; nt++) {
                m = fmaxf(m, sacc[nt][rr*2]);
                m = fmaxf(m, sacc[nt][rr*2+1]);
            }
            m = fmaxf(m, __shfl_xor_sync(0xffffffffu, m, 1));
            m = fmaxf(m, __shfl_xor_sync(0xffffffffu, m, 2));
            mx[rr] = m;
        }
        float nm[2], corr[2], nml[2];
#pragma unroll
        for (int rr = 0; rr < 2; rr++) {
            nm[rr] = fmaxf(m_run[rr], mx[rr]);
            corr[rr] = __expf(m_run[rr] - nm[rr]);
            m_run[rr] = nm[rr];
            nml[rr] = nm[rr] * L2E;
        }
#pragma unroll
        for (int nt = 0; nt < 8; nt++) {
            oacc[nt][0] *= corr[0];
            oacc[nt][1] *= corr[0];
            oacc[nt][2] *= corr[1];
            oacc[nt][3] *= corr[1];
        }
        lacc[0] *= corr[0]; lacc[1] *= corr[0];
        lacc[2] *= corr[1]; lacc[3] *= corr[1];

#pragma unroll
        for (int j = 0; j < 4; j++) {
            uint32_t pa[4];
            pa[0] = ex2_h2(fmaf(sacc[2*j  ][0], L2E, -nml[0]),
                           fmaf(sacc[2*j  ][1], L2E, -nml[0]));
            pa[1] = ex2_h2(fmaf(sacc[2*j  ][2], L2E, -nml[1]),
                           fmaf(sacc[2*j  ][3], L2E, -nml[1]));
            pa[2] = ex2_h2(fmaf(sacc[2*j+1][0], L2E, -nml[0]),
                           fmaf(sacc[2*j+1][1], L2E, -nml[0]));
            pa[3] = ex2_h2(fmaf(sacc[2*j+1][2], L2E, -nml[1]),
                           fmaf(sacc[2*j+1][3], L2E, -nml[1]));
            uint32_t vf[4][4];
#pragma unroll
            for (int p = 0; p < 4; p++)
                ldsm4t(vf[p], vbase + (j * 16 * 36 + p * 8) * 4);
#pragma unroll
            for (int nt = 0; nt < 8; nt++) {
                uint32_t b0 = vf[nt >> 1][(nt & 1) * 2];
                uint32_t b1 = vf[nt >> 1][(nt & 1) * 2 + 1];
                mma_f16(oacc[nt], pa, b0, b1);
            }
            mma_f16(lacc, pa, ONES2, ONES2);
        }
    }

    float inv[2] = {1.f / lacc[0], 1.f / lacc[2]};
#pragma unroll
    for (int nt = 0; nt < 8; nt++)
#pragma unroll
        for (int rr = 0; rr < 2; rr++) {
            int t = t0 + rb + rr * 8 + g;
            int d = nt * 8 + 2 * tg;
            float v0 = oacc[nt][rr*2]     * inv[rr];
            float v1 = oacc[nt][rr*2 + 1] * inv[rr];
            *(uint32_t*)(aT + ((size_t)b * 1024 + t) * 512 + h * 64 + d) = pack_h2(v0, v1);
        }
}

// ---------------------------------------------------------------------------
// proj (R14): 128x128 tile, warp 64x32, 3-stage ring, ldmatrix.
// out[b][m=ch][n=t] = sum_k W[ch][k]*aT[b][t][k] + bias + x
// ---------------------------------------------------------------------------
__global__ __launch_bounds__(256, 2)
void gemm_WA(const __half* __restrict__ W, const __half* __restrict__ Bm,
             const float* __restrict__ bias, const float* __restrict__ res,
             float* __restrict__ out)
{
    extern __shared__ uint32_t sm[];
    const int K = 512, N = 1024;

    int b = blockIdx.z;
    const __half* Bp = Bm + (size_t)b * 1024 * 512;
    float* op = out + (size_t)b * 512 * 1024;
    const float* rp = res + (size_t)b * 512 * 1024;

    int tid = threadIdx.x, w = tid >> 5, lane = tid & 31;
    int g = lane >> 2, tg = lane & 3;
    int warp_m = w >> 2, warp_n = w & 3;
    int m0 = blockIdx.y * 128, n0 = blockIdx.x * 128;
    uint32_t sb = sa32(sm);
    int lr  = (lane & 7) + ((lane >> 3) & 1) * 8;
    int lk  = (lane >> 4) * 4;
    int bnt = lane >> 4;
    int bko = ((lane >> 3) & 1) * 4;
    int br  = lane & 7;

    float acc[4][4][4];
#pragma unroll
    for (int i = 0; i < 4; i++)
#pragma unroll
        for (int j = 0; j < 4; j++)
#pragma unroll
            for (int c = 0; c < 4; c++) acc[i][j][c] = 0.f;

    auto stage = [&](int c, int buf) {
        int OA = buf * 9216, OB = OA + 4608;
        int k0 = c * 64;
#pragma unroll
        for (int it = 0; it < 4; it++) {
            int i = tid + it * 256;
            int row = i >> 3, seg = i & 7;
            cpa16(sb + (OA + row * 36 + seg * 4) * 4,
                  W + (size_t)(m0 + row) * K + k0 + seg * 8);
            cpa16(sb + (OB + row * 36 + seg * 4) * 4,
                  Bp + (size_t)(n0 + row) * K + k0 + seg * 8);
        }
    };

    stage(0, 0); cpa_commit();
    stage(1, 1); cpa_commit();

    for (int c = 0; c < 8; c++) {
        if (c < 7) cpa_wait1(); else cpa_wait0();
        __syncthreads();
        if (c + 2 < 8) { stage(c + 2, (c + 2) % 3); cpa_commit(); }
        int OA = (c % 3) * 9216, OB = OA + 4608;
        uint32_t abase = sb + (OA + (warp_m * 64 + lr) * 36 + lk) * 4;
        uint32_t bbase = sb + (OB + (warp_n * 32 + bnt * 8 + br) * 36 + bko) * 4;
#pragma unroll
        for (int ks = 0; ks < 4; ks++) {
            int kb = ks * 8;
            uint32_t af[4][4];
#pragma unroll
            for (int mt = 0; mt < 4; mt++)
                ldsm4(af[mt], abase + (mt * 16 * 36 + kb) * 4);
            uint32_t bf[2][4];
#pragma unroll
            for (int p = 0; p < 2; p++)
                ldsm4(bf[p], bbase + (p * 16 * 36 + kb) * 4);
#pragma unroll
            for (int nt = 0; nt < 4; nt++) {
                uint32_t b0 = bf[nt >> 1][(nt & 1) * 2];
                uint32_t b1 = bf[nt >> 1][(nt & 1) * 2 + 1];
#pragma unroll
                for (int mt = 0; mt < 4; mt++)
                    mma_f16(acc[mt][nt], af[mt], b0, b1);
            }
        }
    }

#pragma unroll
    for (int mt = 0; mt < 4; mt++) {
#pragma unroll
        for (int rr = 0; rr < 2; rr++) {
            int m = m0 + warp_m * 64 + mt * 16 + rr * 8 + g;
            float bi = bias[m];
#pragma unroll
            for (int nt = 0; nt < 4; nt++) {
#pragma unroll
                for (int ci = 0; ci < 2; ci++) {
                    int n = n0 + warp_n * 32 + nt * 8 + 2 * tg + ci;
                    op[(size_t)m * N + n] = acc[mt][nt][rr * 2 + ci] + bi
                                          + rp[(size_t)m * N + n];
                }
            }
        }
    }
}

// ---------------------------------------------------------------------------
extern "C" void kernel_launch(void* const* d_in, const int* in_sizes, int n_in,
                              void* d_out, int out_size)
{
    const float* x     = (const float*)d_in[0];
    const float* c     = (const float*)d_in[1];
    const float* gamma = (const float*)d_in[2];
    const float* beta  = (const float*)d_in[3];
    const float* w_qkv = (const float*)d_in[4];
    const float* b_qkv = (const float*)d_in[5];
    const float* w_c   = (const float*)d_in[6];
    const float* b_c   = (const float*)d_in[7];
    const float* w_p   = (const float*)d_in[8];
    const float* b_p   = (const float*)d_in[9];
    float* out = (float*)d_out;

    __half *xnT, *qkvT, *cT, *ckvT, *vT, *aT, *wq, *wc, *wp;
    cudaGetSymbolAddress((void**)&xnT,  g_xnT);
    cudaGetSymbolAddress((void**)&qkvT, g_qkvT);
    cudaGetSymbolAddress((void**)&cT,   g_cT);
    cudaGetSymbolAddress((void**)&ckvT, g_ckvT);
    cudaGetSymbolAddress((void**)&vT,   g_vT);
    cudaGetSymbolAddress((void**)&aT,   g_aT);
    cudaGetSymbolAddress((void**)&wq,   g_wq);
    cudaGetSymbolAddress((void**)&wc,   g_wc);
    cudaGetSymbolAddress((void**)&wp,   g_wp);

    static bool attr_done = false;
    if (!attr_done) {
        cudaFuncSetAttribute(groupnorm_kernel, cudaFuncAttributeMaxDynamicSharedMemorySize, 65536);
        cudaFuncSetAttribute(gemm_qkv_ckv, cudaFuncAttributeMaxDynamicSharedMemorySize, 110592);
        cudaFuncSetAttribute(gemm_WA, cudaFuncAttributeMaxDynamicSharedMemorySize, 110592);
        cudaFuncSetAttribute(attn_kernel, cudaFuncAttributeMaxDynamicSharedMemorySize, 73728);
        attr_done = true;
    }

    groupnorm_kernel<<<512, 256, 65536>>>(x, gamma, beta, xnT);
    // weights fp16 conversion (7168 blocks) + cT transpose (1152 blocks), fused
    prep_all<<<7168 + 1152, 256>>>(w_qkv, wq, 1536 * 512,
                                   w_c, wc, 1024 * 768,
                                   w_p, wp, 512 * 512,
                                   c, cT, 7168);

    gemm_qkv_ckv<<<dim3(12, 9, 16), 256, 110592>>>(xnT, wq, b_qkv, cT, wc, b_c,
                                                   qkvT, ckvT, vT);

    attn_kernel<<<dim3(8, 8, 16), 256, 73728>>>(qkvT, ckvT, vT, aT);

    gemm_WA<<<dim3(8, 4, 16), 256, 110592>>>(wp, aT, b_p, x, out);
}

// round 17
// speedup vs baseline: 1.0853x; 1.0090x over previous
#include <cuda_runtime.h>
#include <cuda_fp16.h>
#include <cstdint>

// B=16, C=512, T=1024, L=77, S=1101(pad->1152), HEADS=8, D=64, GROUPS=32, CROSS=768

__device__ __half g_xnT [16 * 1024 * 512];     // [b][t][512]
__device__ __half g_qkvT[16 * 1024 * 1536];    // [b][t][1536]  (q cols pre-scaled x0.125)
__device__ __half g_cT  [16 * 77 * 768];       // [b][l][768]
__device__ __half g_ckvT[16 * 77 * 1024];      // [b][l][1024]
__device__ __half g_vT  [128 * 1152 * 64];     // [bh][s][d]  (BSS zero => pad rows 0)
__device__ __half g_aT  [16 * 1024 * 512];     // [b][t][512]
__device__ __half g_wq[1536 * 512];            // q rows pre-scaled x0.125
__device__ __half g_wc[1024 * 768];
__device__ __half g_wp[512 * 512];
__device__ float  g_bq[1536];                  // b_qkv with q part x0.125

#define DINL __device__ __forceinline__

DINL void mma_f16(float* c, const uint32_t* a, uint32_t b0, uint32_t b1) {
    asm volatile(
        "mma.sync.aligned.m16n8k16.row.col.f32.f16.f16.f32 "
        "{%0,%1,%2,%3},{%4,%5,%6,%7},{%8,%9},{%0,%1,%2,%3};"
        : "+f"(c[0]), "+f"(c[1]), "+f"(c[2]), "+f"(c[3])
        : "r"(a[0]), "r"(a[1]), "r"(a[2]), "r"(a[3]), "r"(b0), "r"(b1));
}
DINL void ldsm4(uint32_t* r, uint32_t addr) {
    asm volatile(
        "ldmatrix.sync.aligned.m8n8.x4.shared.b16 {%0,%1,%2,%3}, [%4];"
        : "=r"(r[0]), "=r"(r[1]), "=r"(r[2]), "=r"(r[3]) : "r"(addr));
}
DINL void ldsm4t(uint32_t* r, uint32_t addr) {
    asm volatile(
        "ldmatrix.sync.aligned.m8n8.x4.trans.shared.b16 {%0,%1,%2,%3}, [%4];"
        : "=r"(r[0]), "=r"(r[1]), "=r"(r[2]), "=r"(r[3]) : "r"(addr));
}
DINL uint32_t pack_h2(float a, float b) {
    __half2 h = __floats2half2_rn(a, b);
    return *(uint32_t*)&h;
}
DINL uint32_t ex2_h2(float a, float b) {
    uint32_t in = pack_h2(a, b), out;
    asm("ex2.approx.f16x2 %0, %1;" : "=r"(out) : "r"(in));
    return out;
}
DINL uint32_t sa32(const void* p) {
    uint32_t a;
    asm("{\n\t.reg .u64 t;\n\tcvta.to.shared.u64 t, %1;\n\tcvt.u32.u64 %0, t;\n\t}"
        : "=r"(a) : "l"(p));
    return a;
}
DINL void cpa16(uint32_t dst, const void* src) {
    asm volatile("cp.async.cg.shared.global [%0], [%1], 16;" :: "r"(dst), "l"(src));
}
DINL void cpa16z(uint32_t dst, const void* src, int sz) {
    asm volatile("cp.async.cg.shared.global [%0], [%1], 16, %2;"
                 :: "r"(dst), "l"(src), "r"(sz));
}
DINL void cpa_commit() { asm volatile("cp.async.commit_group;" ::: "memory"); }
DINL void cpa_wait0()  { asm volatile("cp.async.wait_group 0;" ::: "memory"); }
DINL void cpa_wait1()  { asm volatile("cp.async.wait_group 1;" ::: "memory"); }

// ---------------------------------------------------------------------------
// GroupNorm(32), one global read; normalize + transpose + fp16 from smem.
// ---------------------------------------------------------------------------
__global__ __launch_bounds__(256)
void groupnorm_kernel(const float* __restrict__ x,
                      const float* __restrict__ gamma,
                      const float* __restrict__ beta,
                      __half* __restrict__ xnT)
{
    extern __shared__ float xs[];   // [16][1024]
    int b = blockIdx.x >> 5;
    int g = blockIdx.x & 31;
    const float* xp = x + ((size_t)b * 512 + (size_t)g * 16) * 1024;

    float s = 0.f, s2 = 0.f;
    for (int i = threadIdx.x; i < 16384; i += 256) {
        float v = xp[i];
        xs[i] = v;
        s += v; s2 += v * v;
    }
#pragma unroll
    for (int o = 16; o > 0; o >>= 1) {
        s  += __shfl_xor_sync(0xffffffffu, s, o);
        s2 += __shfl_xor_sync(0xffffffffu, s2, o);
    }
    __shared__ float ss[8], ss2[8];
    __shared__ float smean, sinv;
    int w = threadIdx.x >> 5;
    if ((threadIdx.x & 31) == 0) { ss[w] = s; ss2[w] = s2; }
    __syncthreads();
    if (threadIdx.x == 0) {
        float S = 0.f, S2 = 0.f;
#pragma unroll
        for (int i = 0; i < 8; i++) { S += ss[i]; S2 += ss2[i]; }
        float mean = S * (1.f / 16384.f);
        float var  = S2 * (1.f / 16384.f) - mean * mean;
        smean = mean;
        sinv  = rsqrtf(var + 1e-5f);
    }
    __syncthreads();
    float mean = smean, inv = sinv;

    float gm[16], bt[16];
#pragma unroll
    for (int ch = 0; ch < 16; ch++) {
        gm[ch] = gamma[g * 16 + ch] * inv;
        bt[ch] = beta[g * 16 + ch] - mean * gm[ch];
    }
#pragma unroll
    for (int seg = 0; seg < 4; seg++) {
        int t = seg * 256 + threadIdx.x;
        uint32_t wv[8];
#pragma unroll
        for (int c = 0; c < 8; c++) {
            float v0 = xs[(2 * c)     * 1024 + t] * gm[2 * c]     + bt[2 * c];
            float v1 = xs[(2 * c + 1) * 1024 + t] * gm[2 * c + 1] + bt[2 * c + 1];
            wv[c] = pack_h2(v0, v1);
        }
        __half* dst = xnT + ((size_t)b * 1024 + t) * 512 + g * 16;
        *(uint4*)dst = *(uint4*)&wv[0];
        *(uint4*)(dst + 8) = *(uint4*)&wv[4];
    }
}

// ---------------------------------------------------------------------------
// fused prep: weight fp32->fp16 (q rows x0.125) + c transpose + scaled bias
// blocks [0,nconv): weights; [nconv, nconv+1152): cT; [nconv+1152, +6): bq
// ---------------------------------------------------------------------------
__global__ __launch_bounds__(256)
void prep_all(const float* __restrict__ w0, __half* __restrict__ h0, int n0,
              const float* __restrict__ w1, __half* __restrict__ h1, int n1,
              const float* __restrict__ w2, __half* __restrict__ h2, int n2,
              const float* __restrict__ c, __half* __restrict__ cT,
              const float* __restrict__ b_qkv, float* __restrict__ bq, int nconv)
{
    __shared__ float tile[32][33];
    if ((int)blockIdx.x < nconv) {
        int i = blockIdx.x * 256 + threadIdx.x;
        if (i < n0) {
            float sc = (i < 512 * 512) ? 0.125f : 1.f;   // q rows pre-scaled
            h0[i] = __float2half_rn(w0[i] * sc);
            return;
        }
        i -= n0;
        if (i < n1) { h1[i] = __float2half_rn(w1[i]); return; }
        i -= n1;
        if (i < n2) { h2[i] = __float2half_rn(w2[i]); }
        return;
    }
    int idx = blockIdx.x - nconv;
    if (idx >= 1152) {                          // bias region
        int i = (idx - 1152) * 256 + threadIdx.x;
        if (i < 1536) bq[i] = b_qkv[i] * ((i < 512) ? 0.125f : 1.f);
        return;
    }
    int t0 = (idx % 3) * 32;
    int cb = ((idx / 3) % 24) * 32;
    int b  = idx / 72;
    const float* ip = c + (size_t)b * 768 * 77;
    int tx = threadIdx.x & 31, ty = threadIdx.x >> 5;
#pragma unroll
    for (int i = 0; i < 4; i++) {
        int cr = ty + i * 8;
        tile[cr][tx] = (t0 + tx < 77) ? ip[(size_t)(cb + cr) * 77 + t0 + tx] : 0.f;
    }
    __syncthreads();
#pragma unroll
    for (int i = 0; i < 4; i++) {
        int tr = ty + i * 8;
        if (t0 + tr < 77)
            cT[(size_t)b * 77 * 768 + (size_t)(t0 + tr) * 768 + cb + tx] =
                __float2half_rn(tile[tx][tr]);
    }
}

// ---------------------------------------------------------------------------
// fused qkv + ckv GEMM (R14): 128x128 tile, warp 64x32, 3-stage ring,
// ldmatrix frags; V epilogue writes s-major vT[bh][s][64] coalesced.
// ---------------------------------------------------------------------------
DINL void gemm_at_body(const __half* __restrict__ A, const __half* __restrict__ W,
                       const float* __restrict__ bias, __half* __restrict__ oh,
                       __half* __restrict__ voutB,
                       int Mrows, int K, int ldo, int m0, int n0,
                       int vlo, int sOff, uint32_t sb, uint32_t* sm, int tid)
{
    int w = tid >> 5, lane = tid & 31;
    int g = lane >> 2, tg = lane & 3;
    int warp_m = w >> 2, warp_n = w & 3;
    int lr  = (lane & 7) + ((lane >> 3) & 1) * 8;
    int lk  = (lane >> 4) * 4;
    int bnt = lane >> 4;
    int bko = ((lane >> 3) & 1) * 4;
    int br  = lane & 7;

    float acc[4][4][4];
#pragma unroll
    for (int i = 0; i < 4; i++)
#pragma unroll
        for (int j = 0; j < 4; j++)
#pragma unroll
            for (int c = 0; c < 4; c++) acc[i][j][c] = 0.f;

    int nk = K >> 6;

    auto stage = [&](int c, int buf) {
        int OA = buf * 9216, OB = OA + 4608;
        int k0 = c * 64;
#pragma unroll
        for (int it = 0; it < 4; it++) {
            int i = tid + it * 256;
            int row = i >> 3, seg = i & 7;
            int ar = (m0 + row < Mrows) ? (m0 + row) : 0;
            int sz = (m0 + row < Mrows) ? 16 : 0;
            cpa16z(sb + (OA + row * 36 + seg * 4) * 4,
                   A + (size_t)ar * K + k0 + seg * 8, sz);
            cpa16(sb + (OB + row * 36 + seg * 4) * 4,
                  W + (size_t)(n0 + row) * K + k0 + seg * 8);
        }
    };

    stage(0, 0); cpa_commit();
    stage(1, 1); cpa_commit();

    for (int c = 0; c < nk; c++) {
        if (c < nk - 1) cpa_wait1(); else cpa_wait0();
        __syncthreads();
        if (c + 2 < nk) { stage(c + 2, (c + 2) % 3); cpa_commit(); }
        int OA = (c % 3) * 9216, OB = OA + 4608;
        uint32_t abase = sb + (OA + (warp_m * 64 + lr) * 36 + lk) * 4;
        uint32_t bbase = sb + (OB + (warp_n * 32 + bnt * 8 + br) * 36 + bko) * 4;
#pragma unroll
        for (int ks = 0; ks < 4; ks++) {
            int kb = ks * 8;
            uint32_t af[4][4];
#pragma unroll
            for (int mt = 0; mt < 4; mt++)
                ldsm4(af[mt], abase + (mt * 16 * 36 + kb) * 4);
            uint32_t bf[2][4];
#pragma unroll
            for (int p = 0; p < 2; p++)
                ldsm4(bf[p], bbase + (p * 16 * 36 + kb) * 4);
#pragma unroll
            for (int nt = 0; nt < 4; nt++) {
                uint32_t b0 = bf[nt >> 1][(nt & 1) * 2];
                uint32_t b1 = bf[nt >> 1][(nt & 1) * 2 + 1];
#pragma unroll
                for (int mt = 0; mt < 4; mt++)
                    mma_f16(acc[mt][nt], af[mt], b0, b1);
            }
        }
    }

#pragma unroll
    for (int mt = 0; mt < 4; mt++) {
#pragma unroll
        for (int rr = 0; rr < 2; rr++) {
            int m = m0 + warp_m * 64 + mt * 16 + rr * 8 + g;
            if (m < Mrows) {
#pragma unroll
                for (int nt = 0; nt < 4; nt++) {
                    int n = n0 + warp_n * 32 + nt * 8 + 2 * tg;
                    float v0 = acc[mt][nt][rr * 2]     + bias[n];
                    float v1 = acc[mt][nt][rr * 2 + 1] + bias[n + 1];
                    __half2 hh = __floats2half2_rn(v0, v1);
                    *(uint32_t*)(oh + (size_t)m * ldo + n) = *(uint32_t*)&hh;
                    int d0 = n - vlo;
                    if (d0 >= 0) {
                        size_t o = ((size_t)(d0 >> 6) * 1152 + sOff + m) * 64 + (d0 & 63);
                        *(uint32_t*)(voutB + o) = *(uint32_t*)&hh;
                    }
                }
            }
        }
    }
}

__global__ __launch_bounds__(256, 2)
void gemm_qkv_ckv(const __half* __restrict__ xnT, const __half* __restrict__ wq,
                  const float* __restrict__ bq,
                  const __half* __restrict__ cT, const __half* __restrict__ wc,
                  const float* __restrict__ b_c,
                  __half* __restrict__ qkvT, __half* __restrict__ ckvT,
                  __half* __restrict__ vT)
{
    extern __shared__ uint32_t sm[];
    int b = blockIdx.z;
    uint32_t sb = sa32(sm);
    int tid = threadIdx.x;
    __half* voutB = vT + (size_t)b * 8 * 1152 * 64;

    if (blockIdx.y < 8) {
        gemm_at_body(xnT + (size_t)b * 1024 * 512, wq, bq,
                     qkvT + (size_t)b * 1024 * 1536, voutB,
                     1024, 512, 1536, blockIdx.y * 128, blockIdx.x * 128,
                     1024, 0, sb, sm, tid);
    } else {
        if (blockIdx.x >= 8) return;
        gemm_at_body(cT + (size_t)b * 77 * 768, wc, b_c,
                     ckvT + (size_t)b * 77 * 1024, voutB,
                     77, 768, 1024, 0, blockIdx.x * 128,
                     512, 1024, sb, sm, tid);
    }
}

// ---------------------------------------------------------------------------
// Flash attention (R14 + pre-scaled logits): 256 thr, 128q, 64-key tiles,
// warp = 16q x 64k, P in regs, ex2.f16x2, ones-column row sums,
// ldmatrix (+trans for V), 3-stage cp.async K/V ring, 2 CTAs/SM.
// ---------------------------------------------------------------------------
__global__ __launch_bounds__(256, 2)
void attn_kernel(const __half* __restrict__ qkvT, const __half* __restrict__ ckvT,
                 const __half* __restrict__ vT, __half* __restrict__ aT)
{
    extern __shared__ uint32_t smw[];
    const int OQ = 0;
    const float L2E = 1.4426950408889634f;
    const uint32_t ONES2 = 0x3C003C00u;

    int t0 = blockIdx.x * 128;
    int h  = blockIdx.y;
    int b  = blockIdx.z;
    int bh = b * 8 + h;
    int tid = threadIdx.x;
    int w = tid >> 5, lane = tid & 31;
    int g = lane >> 2, tg = lane & 3;
    uint32_t sb = sa32(smw);
    int lr  = (lane & 7) + ((lane >> 3) & 1) * 8;
    int lk  = (lane >> 4) * 4;
    int bnt = lane >> 4;
    int bko = ((lane >> 3) & 1) * 4;
    int br  = lane & 7;
    int vr  = lane & 15;
    int vkw = (lane >> 4) * 4;

    auto stage_kv = [&](int kt, int buf) {
        int OKb = 4608 + buf * 4608;
        int OVb = OKb + 2304;
        if (kt < 16) {
            const __half* kp = qkvT + ((size_t)b * 1024 + kt * 64) * 1536 + 512 + h * 64;
#pragma unroll
            for (int it = 0; it < 2; it++) {
                int i = tid + it * 256, s = i >> 3, seg = i & 7;
                cpa16(sb + (OKb + s * 36 + seg * 4) * 4, kp + (size_t)s * 1536 + seg * 8);
            }
        } else {
            const __half* kp = ckvT + (size_t)b * 77 * 1024 + h * 64;
            int base = (kt - 16) * 64;
#pragma unroll
            for (int it = 0; it < 2; it++) {
                int i = tid + it * 256, s = i >> 3, seg = i & 7;
                int sl = base + s;
                int sr = (sl < 77) ? sl : 0;
                int sz = (sl < 77) ? 16 : 0;
                cpa16z(sb + (OKb + s * 36 + seg * 4) * 4,
                       kp + (size_t)sr * 1024 + seg * 8, sz);
            }
        }
        const __half* vp = vT + ((size_t)bh * 1152 + kt * 64) * 64;
#pragma unroll
        for (int it = 0; it < 2; it++) {
            int i = tid + it * 256, s = i >> 3, seg = i & 7;
            cpa16(sb + (OVb + s * 36 + seg * 4) * 4, vp + (size_t)s * 64 + seg * 8);
        }
    };

    {
        const __half* qp = qkvT + ((size_t)b * 1024 + t0) * 1536 + h * 64;
#pragma unroll
        for (int it = 0; it < 4; it++) {
            int i = tid + it * 256, row = i >> 3, seg = i & 7;
            cpa16(sb + (OQ + row * 36 + seg * 4) * 4, qp + (size_t)row * 1536 + seg * 8);
        }
    }
    stage_kv(0, 0); cpa_commit();
    stage_kv(1, 1); cpa_commit();

    float oacc[8][4];
#pragma unroll
    for (int nt = 0; nt < 8; nt++)
#pragma unroll
        for (int c = 0; c < 4; c++) oacc[nt][c] = 0.f;
    float lacc[4] = {0.f, 0.f, 0.f, 0.f};
    float m_run[2] = {-1e30f, -1e30f};
    int rb = w * 16;
    uint32_t qbase = sb + (OQ + (rb + lr) * 36 + lk) * 4;

    for (int kt = 0; kt < 18; kt++) {
        if (kt < 17) cpa_wait1(); else cpa_wait0();
        __syncthreads();
        if (kt + 2 < 18) { stage_kv(kt + 2, (kt + 2) % 3); cpa_commit(); }
        int OKb = 4608 + (kt % 3) * 4608;
        int OVb = OKb + 2304;
        uint32_t kbase = sb + (OKb + (bnt * 8 + br) * 36 + bko) * 4;
        uint32_t vbase = sb + (OVb + vr * 36 + vkw) * 4;

        float sacc[8][4];
#pragma unroll
        for (int nt = 0; nt < 8; nt++)
#pragma unroll
            for (int c = 0; c < 4; c++) sacc[nt][c] = 0.f;

#pragma unroll
        for (int ks = 0; ks < 4; ks++) {
            int kb = ks * 8;
            uint32_t af[4];
            ldsm4(af, qbase + kb * 4);
            uint32_t bf[4][4];
#pragma unroll
            for (int p = 0; p < 4; p++)
                ldsm4(bf[p], kbase + (p * 16 * 36 + kb) * 4);
#pragma unroll
            for (int nt = 0; nt < 8; nt++) {
                uint32_t b0 = bf[nt >> 1][(nt & 1) * 2];
                uint32_t b1 = bf[nt >> 1][(nt & 1) * 2 + 1];
                mma_f16(sacc[nt], af, b0, b1);
            }
        }

        // logits already scaled (Q weights pre-scaled x0.125); only mask last tile
        if (kt == 17) {
#pragma unroll
            for (int nt = 0; nt < 8; nt++)
#pragma unroll
                for (int c = 0; c < 4; c++)
                    if ((nt * 8 + 2 * tg + (c & 1)) >= 13) sacc[nt][c] = -1e30f;
        }

        float mx[2];
#pragma unroll
        for (int rr = 0; rr < 2; rr++) {
            float m = fmaxf(sacc[0][rr*2], sacc[0][rr*2+1]);
#pragma unroll
            for (int nt = 1; nt < 8; nt++) {
                m = fmaxf(m, sacc[nt][rr*2]);
                m = fmaxf(m, sacc[nt][rr*2+1]);
            }
            m = fmaxf(m, __shfl_xor_sync(0xffffffffu, m, 1));
            m = fmaxf(m, __shfl_xor_sync(0xffffffffu, m, 2));
            mx[rr] = m;
        }
        float nm[2], corr[2], nml[2];
#pragma unroll
        for (int rr = 0; rr < 2; rr++) {
            nm[rr] = fmaxf(m_run[rr], mx[rr]);
            corr[rr] = __expf(m_run[rr] - nm[rr]);
            m_run[rr] = nm[rr];
            nml[rr] = nm[rr] * L2E;
        }
#pragma unroll
        for (int nt = 0; nt < 8; nt++) {
            oacc[nt][0] *= corr[0];
            oacc[nt][1] *= corr[0];
            oacc[nt][2] *= corr[1];
            oacc[nt][3] *= corr[1];
        }
        lacc[0] *= corr[0]; lacc[1] *= corr[0];
        lacc[2] *= corr[1]; lacc[3] *= corr[1];

#pragma unroll
        for (int j = 0; j < 4; j++) {
            uint32_t pa[4];
            pa[0] = ex2_h2(fmaf(sacc[2*j  ][0], L2E, -nml[0]),
                           fmaf(sacc[2*j  ][1], L2E, -nml[0]));
            pa[1] = ex2_h2(fmaf(sacc[2*j  ][2], L2E, -nml[1]),
                           fmaf(sacc[2*j  ][3], L2E, -nml[1]));
            pa[2] = ex2_h2(fmaf(sacc[2*j+1][0], L2E, -nml[0]),
                           fmaf(sacc[2*j+1][1], L2E, -nml[0]));
            pa[3] = ex2_h2(fmaf(sacc[2*j+1][2], L2E, -nml[1]),
                           fmaf(sacc[2*j+1][3], L2E, -nml[1]));
            uint32_t vf[4][4];
#pragma unroll
            for (int p = 0; p < 4; p++)
                ldsm4t(vf[p], vbase + (j * 16 * 36 + p * 8) * 4);
#pragma unroll
            for (int nt = 0; nt < 8; nt++) {
                uint32_t b0 = vf[nt >> 1][(nt & 1) * 2];
                uint32_t b1 = vf[nt >> 1][(nt & 1) * 2 + 1];
                mma_f16(oacc[nt], pa, b0, b1);
            }
            mma_f16(lacc, pa, ONES2, ONES2);
        }
    }

    float inv[2] = {1.f / lacc[0], 1.f / lacc[2]};
#pragma unroll
    for (int nt = 0; nt < 8; nt++)
#pragma unroll
        for (int rr = 0; rr < 2; rr++) {
            int t = t0 + rb + rr * 8 + g;
            int d = nt * 8 + 2 * tg;
            float v0 = oacc[nt][rr*2]     * inv[rr];
            float v1 = oacc[nt][rr*2 + 1] * inv[rr];
            *(uint32_t*)(aT + ((size_t)b * 1024 + t) * 512 + h * 64 + d) = pack_h2(v0, v1);
        }
}

// ---------------------------------------------------------------------------
// proj (R14): 128x128 tile, warp 64x32, 3-stage ring, ldmatrix.
// out[b][m=ch][n=t] = sum_k W[ch][k]*aT[b][t][k] + bias + x
// ---------------------------------------------------------------------------
__global__ __launch_bounds__(256, 2)
void gemm_WA(const __half* __restrict__ W, const __half* __restrict__ Bm,
             const float* __restrict__ bias, const float* __restrict__ res,
             float* __restrict__ out)
{
    extern __shared__ uint32_t sm[];
    const int K = 512, N = 1024;

    int b = blockIdx.z;
    const __half* Bp = Bm + (size_t)b * 1024 * 512;
    float* op = out + (size_t)b * 512 * 1024;
    const float* rp = res + (size_t)b * 512 * 1024;

    int tid = threadIdx.x, w = tid >> 5, lane = tid & 31;
    int g = lane >> 2, tg = lane & 3;
    int warp_m = w >> 2, warp_n = w & 3;
    int m0 = blockIdx.y * 128, n0 = blockIdx.x * 128;
    uint32_t sb = sa32(sm);
    int lr  = (lane & 7) + ((lane >> 3) & 1) * 8;
    int lk  = (lane >> 4) * 4;
    int bnt = lane >> 4;
    int bko = ((lane >> 3) & 1) * 4;
    int br  = lane & 7;

    float acc[4][4][4];
#pragma unroll
    for (int i = 0; i < 4; i++)
#pragma unroll
        for (int j = 0; j < 4; j++)
#pragma unroll
            for (int c = 0; c < 4; c++) acc[i][j][c] = 0.f;

    auto stage = [&](int c, int buf) {
        int OA = buf * 9216, OB = OA + 4608;
        int k0 = c * 64;
#pragma unroll
        for (int it = 0; it < 4; it++) {
            int i = tid + it * 256;
            int row = i >> 3, seg = i & 7;
            cpa16(sb + (OA + row * 36 + seg * 4) * 4,
                  W + (size_t)(m0 + row) * K + k0 + seg * 8);
            cpa16(sb + (OB + row * 36 + seg * 4) * 4,
                  Bp + (size_t)(n0 + row) * K + k0 + seg * 8);
        }
    };

    stage(0, 0); cpa_commit();
    stage(1, 1); cpa_commit();

    for (int c = 0; c < 8; c++) {
        if (c < 7) cpa_wait1(); else cpa_wait0();
        __syncthreads();
        if (c + 2 < 8) { stage(c + 2, (c + 2) % 3); cpa_commit(); }
        int OA = (c % 3) * 9216, OB = OA + 4608;
        uint32_t abase = sb + (OA + (warp_m * 64 + lr) * 36 + lk) * 4;
        uint32_t bbase = sb + (OB + (warp_n * 32 + bnt * 8 + br) * 36 + bko) * 4;
#pragma unroll
        for (int ks = 0; ks < 4; ks++) {
            int kb = ks * 8;
            uint32_t af[4][4];
#pragma unroll
            for (int mt = 0; mt < 4; mt++)
                ldsm4(af[mt], abase + (mt * 16 * 36 + kb) * 4);
            uint32_t bf[2][4];
#pragma unroll
            for (int p = 0; p < 2; p++)
                ldsm4(bf[p], bbase + (p * 16 * 36 + kb) * 4);
#pragma unroll
            for (int nt = 0; nt < 4; nt++) {
                uint32_t b0 = bf[nt >> 1][(nt & 1) * 2];
                uint32_t b1 = bf[nt >> 1][(nt & 1) * 2 + 1];
#pragma unroll
                for (int mt = 0; mt < 4; mt++)
                    mma_f16(acc[mt][nt], af[mt], b0, b1);
            }
        }
    }

#pragma unroll
    for (int mt = 0; mt < 4; mt++) {
#pragma unroll
        for (int rr = 0; rr < 2; rr++) {
            int m = m0 + warp_m * 64 + mt * 16 + rr * 8 + g;
            float bi = bias[m];
#pragma unroll
            for (int nt = 0; nt < 4; nt++) {
#pragma unroll
                for (int ci = 0; ci < 2; ci++) {
                    int n = n0 + warp_n * 32 + nt * 8 + 2 * tg + ci;
                    op[(size_t)m * N + n] = acc[mt][nt][rr * 2 + ci] + bi
                                          + rp[(size_t)m * N + n];
                }
            }
        }
    }
}

// ---------------------------------------------------------------------------
extern "C" void kernel_launch(void* const* d_in, const int* in_sizes, int n_in,
                              void* d_out, int out_size)
{
    const float* x     = (const float*)d_in[0];
    const float* c     = (const float*)d_in[1];
    const float* gamma = (const float*)d_in[2];
    const float* beta  = (const float*)d_in[3];
    const float* w_qkv = (const float*)d_in[4];
    const float* b_qkv = (const float*)d_in[5];
    const float* w_c   = (const float*)d_in[6];
    const float* b_c   = (const float*)d_in[7];
    const float* w_p   = (const float*)d_in[8];
    const float* b_p   = (const float*)d_in[9];
    float* out = (float*)d_out;

    __half *xnT, *qkvT, *cT, *ckvT, *vT, *aT, *wq, *wc, *wp;
    float* bq;
    cudaGetSymbolAddress((void**)&xnT,  g_xnT);
    cudaGetSymbolAddress((void**)&qkvT, g_qkvT);
    cudaGetSymbolAddress((void**)&cT,   g_cT);
    cudaGetSymbolAddress((void**)&ckvT, g_ckvT);
    cudaGetSymbolAddress((void**)&vT,   g_vT);
    cudaGetSymbolAddress((void**)&aT,   g_aT);
    cudaGetSymbolAddress((void**)&wq,   g_wq);
    cudaGetSymbolAddress((void**)&wc,   g_wc);
    cudaGetSymbolAddress((void**)&wp,   g_wp);
    cudaGetSymbolAddress((void**)&bq,   g_bq);

    static bool attr_done = false;
    if (!attr_done) {
        cudaFuncSetAttribute(groupnorm_kernel, cudaFuncAttributeMaxDynamicSharedMemorySize, 65536);
        cudaFuncSetAttribute(gemm_qkv_ckv, cudaFuncAttributeMaxDynamicSharedMemorySize, 110592);
        cudaFuncSetAttribute(gemm_WA, cudaFuncAttributeMaxDynamicSharedMemorySize, 110592);
        cudaFuncSetAttribute(attn_kernel, cudaFuncAttributeMaxDynamicSharedMemorySize, 73728);
        attr_done = true;
    }

    groupnorm_kernel<<<512, 256, 65536>>>(x, gamma, beta, xnT);
    prep_all<<<7168 + 1152 + 6, 256>>>(w_qkv, wq, 1536 * 512,
                                       w_c, wc, 1024 * 768,
                                       w_p, wp, 512 * 512,
                                       c, cT, b_qkv, bq, 7168);

    gemm_qkv_ckv<<<dim3(12, 9, 16), 256, 110592>>>(xnT, wq, bq, cT, wc, b_c,
                                                   qkvT, ckvT, vT);

    attn_kernel<<<dim3(8, 8, 16), 256, 73728>>>(qkvT, ckvT, vT, aT);

    gemm_WA<<<dim3(8, 4, 16), 256, 110592>>>(wp, aT, b_p, x, out);
}